// round 7
// baseline (speedup 1.0000x reference)
#include <cuda_runtime.h>
#include <cuda_bf16.h>
#include <cstdint>

typedef unsigned long long u64;

// ---------------- static scratch ----------------
// activation planes, layout (p, b, c): elem (p*128+b)*256+c, bf16 hi/lo split
__device__ __align__(16) __nv_bfloat16 g_hA[16777216];   // 33.5 MB (512 pos)
__device__ __align__(16) __nv_bfloat16 g_lA[16777216];
__device__ __align__(16) __nv_bfloat16 g_hB[8388608];    // (256 pos)
__device__ __align__(16) __nv_bfloat16 g_lB[8388608];
__device__ __align__(16) float g_part[4194304];          // split-K partials
// weight images: per (layer, d, oh, stage): 16KB swizzled smem image (bf16 hi/lo)
// total for layers 1..9: 511 * 512KB = 261.6MB
__device__ __align__(16) __nv_bfloat16 g_wimg[134217728];

// ---------------- helpers ----------------
__device__ __forceinline__ uint32_t s2u(const void* p) {
    uint32_t a;
    asm("{\n\t.reg .u64 t;\n\tcvta.to.shared.u64 t, %1;\n\tcvt.u32.u64 %0, t;\n\t}" : "=r"(a) : "l"(p));
    return a;
}
__device__ __forceinline__ uint32_t packbf(float lo, float hi) {
    uint32_t r;
    asm("cvt.rn.bf16x2.f32 %0, %1, %2;" : "=r"(r) : "f"(hi), "f"(lo));
    return r;
}
__device__ __forceinline__ void split2(float x0, float x1, uint32_t& hi, uint32_t& lo) {
    uint32_t h = packbf(x0, x1);
    __nv_bfloat162 h2 = *(__nv_bfloat162*)&h;
    lo = packbf(x0 - __bfloat162float(h2.x), x1 - __bfloat162float(h2.y));
    hi = h;
}
__device__ __forceinline__ void ldsm4(uint32_t* r, uint32_t addr) {
    asm volatile("ldmatrix.sync.aligned.m8n8.x4.shared.b16 {%0,%1,%2,%3}, [%4];"
        : "=r"(r[0]), "=r"(r[1]), "=r"(r[2]), "=r"(r[3]) : "r"(addr));
}
__device__ __forceinline__ void mma16816(float* d, const uint32_t* a, uint32_t b0, uint32_t b1) {
    asm volatile("mma.sync.aligned.m16n8k16.row.col.f32.bf16.bf16.f32 "
        "{%0,%1,%2,%3}, {%4,%5,%6,%7}, {%8,%9}, {%0,%1,%2,%3};"
        : "+f"(d[0]), "+f"(d[1]), "+f"(d[2]), "+f"(d[3])
        : "r"(a[0]), "r"(a[1]), "r"(a[2]), "r"(a[3]), "r"(b0), "r"(b1));
}
__device__ __forceinline__ void cpasync16(uint32_t dst, const void* src) {
    asm volatile("cp.async.cg.shared.global [%0], [%1], 16;" :: "r"(dst), "l"(src) : "memory");
}
__device__ __forceinline__ void cpcommit() {
    asm volatile("cp.async.commit_group;" ::: "memory");
}
__device__ __forceinline__ void cpwait2() {
    asm volatile("cp.async.wait_group 2;" ::: "memory");
}

// ---------------- weight prep: fp32 (o,c,dl,2) -> per-(d,oh,stage) 16KB bf16 image ----
// Image layout (matches R6 b_store exactly): row r = o_local (128 rows x 128B),
//   byte within row for (c_local 0..15, k 0..1, plane hi=0/lo=1):
//     chunk = (plane*64 + k*32 + (c_local>>3)*16) ^ ((r&7)<<4);  byte = r*128 + chunk + (c_local&7)*2
// Image index: ((d*2 + oh)*16 + t) * 16384 bytes.
__global__ __launch_bounds__(256, 1)
void wprep(const float* __restrict__ w, __nv_bfloat16* __restrict__ img, int dl, int DB)
{
    extern __shared__ char ps[];              // DB * 8192 bytes (<= 64KB)
    const int tid = threadIdx.x;
    const int d0  = blockIdx.x * DB;
    const int ohh = blockIdx.y;
    const int t   = blockIdx.z;

    for (int half = 0; half < 2; half++) {
        // read + convert + smem-store: 64 o x 16 c x DB d x 2 k
#pragma unroll
        for (int it = 0; it < 4; it++) {
            const int item  = it * 256 + tid;        // 1024 items
            const int o_sub = item >> 4;
            const int c_l   = item & 15;
            const int o = ohh * 128 + half * 64 + o_sub;
            const int c = t * 16 + c_l;
            const float2* src = (const float2*)(w + (((size_t)o * 256 + c) * dl + d0) * 2);
            const uint32_t sw = (uint32_t)(o_sub & 7) << 4;
            const uint32_t cl2 = (uint32_t)(c_l & 7) * 2;
            const uint32_t chH0 = ((0u * 32 + 0u + ((uint32_t)(c_l >> 3)) * 16) ^ sw);
            const uint32_t chH1 = ((1u * 32 + 0u + ((uint32_t)(c_l >> 3)) * 16) ^ sw);
            const uint32_t chL0 = ((0u * 32 + 64u + ((uint32_t)(c_l >> 3)) * 16) ^ sw);
            const uint32_t chL1 = ((1u * 32 + 64u + ((uint32_t)(c_l >> 3)) * 16) ^ sw);
            const uint32_t rb = (uint32_t)o_sub * 128;
            for (int dd = 0; dd < DB; dd++) {
                float2 v = src[dd];
                uint32_t base = (uint32_t)dd * 8192 + rb;
                __nv_bfloat16 h0 = __float2bfloat16(v.x);
                __nv_bfloat16 h1 = __float2bfloat16(v.y);
                __nv_bfloat16 l0 = __float2bfloat16(v.x - __bfloat162float(h0));
                __nv_bfloat16 l1 = __float2bfloat16(v.y - __bfloat162float(h1));
                *(__nv_bfloat16*)(ps + base + chH0 + cl2) = h0;
                *(__nv_bfloat16*)(ps + base + chH1 + cl2) = h1;
                *(__nv_bfloat16*)(ps + base + chL0 + cl2) = l0;
                *(__nv_bfloat16*)(ps + base + chL1 + cl2) = l1;
            }
        }
        __syncthreads();
        // write out: DB half-images of 8KB, coalesced 16B chunks
        const int nchunks = DB * 512;             // 16B chunks total
        for (int j = tid; j < nchunks; j += 256) {
            const int byte = j * 16;
            const int dd   = byte >> 13;
            const int off  = byte & 8191;
            char* dst = (char*)img + (((size_t)(d0 + dd) * 2 + ohh) * 16 + t) * 16384
                        + half * 8192 + off;
            *(float4*)dst = *(const float4*)(ps + byte);
        }
        __syncthreads();
    }
}

// ---------------- layer 0: fp32 -> bf16 planes ----------------
__global__ void layer0_kernel(const float* __restrict__ x, const float* __restrict__ w0,
                              __nv_bfloat16* __restrict__ oh_, __nv_bfloat16* __restrict__ ol_)
{
    __shared__ float xs[6][128];
    const int d   = blockIdx.x;
    const int tid = threadIdx.x;
#pragma unroll
    for (int i = 0; i < 3; i++) {
        int e = tid + i * 256;
        int ck = e >> 7, b = e & 127;
        int c = ck >> 1, k = ck & 1;
        xs[ck][b] = x[(b * 3 + c) * 1024 + 2 * d + k];
    }
    __syncthreads();
    const int b   = tid & 127;
    const int ohh = tid >> 7;
    const float2* w2 = (const float2*)w0;
    for (int o = ohh; o < 256; o += 2) {
        float acc = 0.f;
#pragma unroll
        for (int c = 0; c < 3; c++) {
            float2 wv = w2[(o * 3 + c) * 512 + d];
            acc += xs[c * 2 + 0][b] * wv.x + xs[c * 2 + 1][b] * wv.y;
        }
        float v = fmaxf(acc * 0.5773502691896258f, 0.f);
        __nv_bfloat16 h = __float2bfloat16(v);
        size_t idx = ((size_t)d * 128 + b) * 256 + o;
        oh_[idx] = h;
        ol_[idx] = __float2bfloat16(v - __bfloat162float(h));
    }
}

// ---------------- layers 1..9: warp-mma bf16x3, all-cp.async pipeline ----------------
// A planes (p,b,c) bf16 hi/lo; B = prebuilt weight images.
// CTA: M=128(b) x N=128(o half) x K-slice (nst stages x 32 kappa).
// smem: 3-deep ring of (A 16KB + B 16KB) = 96KB.
#define SMEM_G 98304

__global__ __launch_bounds__(256, 1)
void lc_mma(const __nv_bfloat16* __restrict__ gh, const __nv_bfloat16* __restrict__ gl,
            const __nv_bfloat16* __restrict__ wimg,
            __nv_bfloat16* __restrict__ oh_, __nv_bfloat16* __restrict__ ol_,
            int dl, int nst, float scale, int partial)
{
    extern __shared__ __align__(1024) char smem[];
    const uint32_t sb = s2u(smem);
    const int tid  = threadIdx.x;
    const int wid  = tid >> 5, lane = tid & 31;
    const int oh   = blockIdx.x;
    const int d    = blockIdx.y;
    const int s    = blockIdx.z;
    const int tg0  = s * nst;                 // global stage base

    // ---- loader roles: row r (0..127), half h (0..1) ----
    const int r = tid >> 1;
    const int h = tid & 1;
    const uint32_t rowb = (uint32_t)r * 128, xsw = (uint32_t)(r & 7) << 4;
    const uint32_t offs[4] = {
        rowb + ((0u * 32 + 0u * 64 + (uint32_t)h * 16) ^ xsw),   // k0 hi
        rowb + ((1u * 32 + 0u * 64 + (uint32_t)h * 16) ^ xsw),   // k1 hi
        rowb + ((0u * 32 + 1u * 64 + (uint32_t)h * 16) ^ xsw),   // k0 lo
        rowb + ((1u * 32 + 1u * 64 + (uint32_t)h * 16) ^ xsw)    // k1 lo
    };
    const size_t arow0 = ((size_t)(2 * d) * 128 + r) * 256;
    const size_t arow1 = arow0 + 128 * 256;
    const __nv_bfloat16* asrc[4] = { gh + arow0, gh + arow1, gl + arow0, gl + arow1 };
    const char* imgd = (const char*)wimg + (((size_t)d * 2 + oh) * 16 + tg0) * 16384;

    // ---- compute roles: 2x4 warps, warp tile 64x32 ----
    const int mh = wid & 1, nq = wid >> 1;
    const uint32_t co = (uint32_t)(lane >> 4) * 16;
    const uint32_t xa = (uint32_t)(lane & 7) << 4;
    uint32_t rA[4], rB[2];
#pragma unroll
    for (int mi = 0; mi < 4; mi++) rA[mi] = (uint32_t)(mh * 64 + mi * 16 + (lane & 15)) * 128;
#pragma unroll
    for (int bj = 0; bj < 2; bj++) rB[bj] = (uint32_t)(nq * 32 + bj * 16 + (lane & 15)) * 128;

    float D[4][4][4];
#pragma unroll
    for (int i = 0; i < 4; i++)
#pragma unroll
        for (int j = 0; j < 4; j++)
#pragma unroll
            for (int q = 0; q < 4; q++) D[i][j][q] = 0.f;

    auto stage_issue = [&](int t, int slot) {
        const uint32_t ad = sb + (uint32_t)slot * 32768;
        const uint32_t bd = ad + 16384;
        const int c0 = (tg0 + t) * 16 + 8 * h;
        const char* bsrc = imgd + (size_t)t * 16384;
#pragma unroll
        for (int i = 0; i < 4; i++) {
            cpasync16(ad + offs[i], asrc[i] + c0);
            cpasync16(bd + offs[i], bsrc + offs[i]);
        }
    };

    // ---- prologue: 3 groups ----
#pragma unroll
    for (int ps = 0; ps < 3; ps++) {
        if (ps < nst) stage_issue(ps, ps);
        cpcommit();
    }

    // ---- main loop ----
    int slot = 0;
    for (int t = 0; t < nst; t++) {
        cpwait2();
        __syncthreads();

        const uint32_t ab = sb + (uint32_t)slot * 32768;
        const uint32_t bb = ab + 16384;
#pragma unroll
        for (int kk = 0; kk < 2; kk++) {
            uint32_t Ahf[4][4], Alf[4][4], Bhf[2][4], Blf[2][4];
            const uint32_t khi = (uint32_t)(32 * kk) + co;
            const uint32_t klo = khi + 64;
#pragma unroll
            for (int mi = 0; mi < 4; mi++) {
                ldsm4(Ahf[mi], ab + rA[mi] + (khi ^ xa));
                ldsm4(Alf[mi], ab + rA[mi] + (klo ^ xa));
            }
#pragma unroll
            for (int bj = 0; bj < 2; bj++) {
                ldsm4(Bhf[bj], bb + rB[bj] + (khi ^ xa));
                ldsm4(Blf[bj], bb + rB[bj] + (klo ^ xa));
            }
#pragma unroll
            for (int mi = 0; mi < 4; mi++) {
#pragma unroll
                for (int nj = 0; nj < 4; nj++) {
                    const int bt = nj >> 1, bs = nj & 1;
                    mma16816(D[mi][nj], Ahf[mi], Bhf[bt][bs], Bhf[bt][bs + 2]);
                    mma16816(D[mi][nj], Alf[mi], Bhf[bt][bs], Bhf[bt][bs + 2]);
                    mma16816(D[mi][nj], Ahf[mi], Blf[bt][bs], Blf[bt][bs + 2]);
                }
            }
        }
        __syncthreads();                       // all warps done with this slot
        if (t + 3 < nst) stage_issue(t + 3, slot);
        cpcommit();
        slot = (slot + 1 == 3) ? 0 : slot + 1;
    }

    // ---- epilogue ----
    const int colq = nq * 32 + 2 * (lane & 3);
    if (partial) {
        float* pp = g_part + ((size_t)(s * 2 + oh) * dl + d) * 16384;
#pragma unroll
        for (int mi = 0; mi < 4; mi++) {
            const int b0 = mh * 64 + mi * 16 + (lane >> 2);
#pragma unroll
            for (int nj = 0; nj < 4; nj++) {
                const int col = colq + nj * 8;
                *(float2*)(pp + (size_t)b0 * 128 + col)       = make_float2(D[mi][nj][0], D[mi][nj][1]);
                *(float2*)(pp + (size_t)(b0 + 8) * 128 + col) = make_float2(D[mi][nj][2], D[mi][nj][3]);
            }
        }
    } else {
#pragma unroll
        for (int mi = 0; mi < 4; mi++) {
            const int b0 = mh * 64 + mi * 16 + (lane >> 2);
#pragma unroll
            for (int nj = 0; nj < 4; nj++) {
                const int col = oh * 128 + colq + nj * 8;
                float v00 = fmaxf(D[mi][nj][0] * scale, 0.f);
                float v01 = fmaxf(D[mi][nj][1] * scale, 0.f);
                float v10 = fmaxf(D[mi][nj][2] * scale, 0.f);
                float v11 = fmaxf(D[mi][nj][3] * scale, 0.f);
                uint32_t h0, l0, h1, l1;
                split2(v00, v01, h0, l0);
                split2(v10, v11, h1, l1);
                size_t i0 = ((size_t)d * 128 + b0) * 256 + col;
                size_t i1 = i0 + 8 * 256;
                *(uint32_t*)(oh_ + i0) = h0;  *(uint32_t*)(ol_ + i0) = l0;
                *(uint32_t*)(oh_ + i1) = h1;  *(uint32_t*)(ol_ + i1) = l1;
            }
        }
    }
}

// ---------------- split-K reduce + relu -> bf16 planes ----------------
__global__ void reduce_relu_kernel(const float* __restrict__ part,
                                   __nv_bfloat16* __restrict__ oh_, __nv_bfloat16* __restrict__ ol_,
                                   int n, int dl, int S, float scale)
{
    int idx = blockIdx.x * 256 + threadIdx.x;
    if (idx >= n) return;
    const int o  = idx & 255;
    const int b  = (idx >> 8) & 127;
    const int dd = idx >> 15;
    const int ohh = o >> 7, ol = o & 127;
    float sum = 0.f;
    for (int si = 0; si < S; si++)
        sum += part[((size_t)(si * 2 + ohh) * dl + dd) * 16384 + b * 128 + ol];
    float v = fmaxf(sum * scale, 0.f);
    __nv_bfloat16 hh = __float2bfloat16(v);
    oh_[idx] = hh;
    ol_[idx] = __float2bfloat16(v - __bfloat162float(hh));
}

// ---------------- head ----------------
__global__ void head_kernel(const __nv_bfloat16* __restrict__ ah, const __nv_bfloat16* __restrict__ al,
                            const float* __restrict__ beta, float* __restrict__ out)
{
    const int t = blockIdx.x;
    const int b = threadIdx.x;
    float s = 0.f;
#pragma unroll 8
    for (int o = 0; o < 256; o++) {
        float v = __bfloat162float(ah[b * 256 + o]) + __bfloat162float(al[b * 256 + o]);
        s += v * __ldg(&beta[o * 10 + t]);
    }
    out[b * 10 + t] = s * (1.0f / 256.0f);
}

// ---------------- launch ----------------
extern "C" void kernel_launch(void* const* d_in, const int* in_sizes, int n_in,
                              void* d_out, int out_size)
{
    const float* x = (const float*)d_in[0];
    const float* wl[10];
    for (int l = 0; l < 10; l++) wl[l] = (const float*)d_in[1 + l];
    const float* beta = (const float*)d_in[11];
    float* out = (float*)d_out;

    __nv_bfloat16 *hA, *lA, *hB, *lB, *wimg;
    float* part;
    cudaGetSymbolAddress((void**)&hA, g_hA);
    cudaGetSymbolAddress((void**)&lA, g_lA);
    cudaGetSymbolAddress((void**)&hB, g_hB);
    cudaGetSymbolAddress((void**)&lB, g_lB);
    cudaGetSymbolAddress((void**)&wimg, g_wimg);
    cudaGetSymbolAddress((void**)&part, g_part);

    cudaFuncSetAttribute(lc_mma, cudaFuncAttributeMaxDynamicSharedMemorySize, SMEM_G);
    cudaFuncSetAttribute(wprep, cudaFuncAttributeMaxDynamicSharedMemorySize, 65536);

    // ---- weight prep for layers 1..9 ----
    size_t wbase[10];
    {
        size_t off = 0;
        int dl = 256;
        for (int l = 1; l <= 9; l++) {
            wbase[l] = off;
            off += (size_t)dl * 262144;        // elems per layer: dl * 2oh * 16t * 8192
            int DB = dl < 8 ? dl : 8;
            wprep<<<dim3(dl / DB, 2, 16), 256, DB * 8192>>>(wl[l], wimg + wbase[l], dl, DB);
            dl >>= 1;
        }
    }

    layer0_kernel<<<512, 256>>>(x, wl[0], hA, lA);

    __nv_bfloat16 *curH = hA, *curL = lA, *nxtH = hB, *nxtL = lB;
    int dl = 256;
    const float scale = 0.0625f;
    for (int l = 1; l <= 9; l++) {
        int S;
        if (dl >= 128)      S = 1;
        else if (dl == 64)  S = 2;
        else if (dl == 32)  S = 4;
        else                S = 8;
        const int nst = 16 / S;
        if (S == 1) {
            lc_mma<<<dim3(2, dl, 1), 256, SMEM_G>>>(curH, curL, wimg + wbase[l], nxtH, nxtL, dl, nst, scale, 0);
        } else {
            lc_mma<<<dim3(2, dl, S), 256, SMEM_G>>>(curH, curL, wimg + wbase[l], nullptr, nullptr, dl, nst, scale, 1);
            const int n = dl * 32768;
            reduce_relu_kernel<<<(n + 255) / 256, 256>>>(part, nxtH, nxtL, n, dl, S, scale);
        }
        __nv_bfloat16* t;
        t = curH; curH = nxtH; nxtH = t;
        t = curL; curL = nxtL; nxtL = t;
        dl >>= 1;
    }

    head_kernel<<<10, 128>>>(curH, curL, beta, out);
}

// round 8
// speedup vs baseline: 1.4089x; 1.4089x over previous
#include <cuda_runtime.h>
#include <cuda_bf16.h>
#include <cstdint>

typedef unsigned long long u64;

// ---------------- static scratch ----------------
// activations layout: (p, b, c) : act[(p*128 + b)*256 + c]
__device__ __align__(16) float g_bufA[512 * 128 * 256];   // 67 MB
__device__ __align__(16) float g_bufB[256 * 128 * 256];   // 33.5 MB
__device__ __align__(16) float g_part[4194304];           // 16.8 MB split-K partials

// ---------------- helpers ----------------
__device__ __forceinline__ uint32_t s2u(const void* p) {
    uint32_t a;
    asm("{\n\t.reg .u64 t;\n\tcvta.to.shared.u64 t, %1;\n\tcvt.u32.u64 %0, t;\n\t}" : "=r"(a) : "l"(p));
    return a;
}
// pack: first arg -> low bf16 half, second -> high half
__device__ __forceinline__ uint32_t packbf(float lo, float hi) {
    uint32_t r;
    asm("cvt.rn.bf16x2.f32 %0, %1, %2;" : "=r"(r) : "f"(hi), "f"(lo));
    return r;
}
__device__ __forceinline__ void split2(float x0, float x1, uint32_t& hi, uint32_t& lo) {
    uint32_t h = packbf(x0, x1);
    __nv_bfloat162 h2 = *(__nv_bfloat162*)&h;
    float r0 = x0 - __bfloat162float(h2.x);
    float r1 = x1 - __bfloat162float(h2.y);
    lo = packbf(r0, r1);
    hi = h;
}
__device__ __forceinline__ void ldsm4(uint32_t* r, uint32_t addr) {
    asm volatile("ldmatrix.sync.aligned.m8n8.x4.shared.b16 {%0,%1,%2,%3}, [%4];"
        : "=r"(r[0]), "=r"(r[1]), "=r"(r[2]), "=r"(r[3]) : "r"(addr));
}
__device__ __forceinline__ void mma16816(float* d, const uint32_t* a, uint32_t b0, uint32_t b1) {
    asm volatile("mma.sync.aligned.m16n8k16.row.col.f32.bf16.bf16.f32 "
        "{%0,%1,%2,%3}, {%4,%5,%6,%7}, {%8,%9}, {%0,%1,%2,%3};"
        : "+f"(d[0]), "+f"(d[1]), "+f"(d[2]), "+f"(d[3])
        : "r"(a[0]), "r"(a[1]), "r"(a[2]), "r"(a[3]), "r"(b0), "r"(b1));
}

// ---------------- layer 0 ----------------
__global__ void layer0_kernel(const float* __restrict__ x, const float* __restrict__ w0,
                              float* __restrict__ out)
{
    __shared__ float xs[6][128];
    const int d   = blockIdx.x;
    const int tid = threadIdx.x;
#pragma unroll
    for (int i = 0; i < 3; i++) {
        int e = tid + i * 256;
        int ck = e >> 7, b = e & 127;
        int c = ck >> 1, k = ck & 1;
        xs[ck][b] = x[(b * 3 + c) * 1024 + 2 * d + k];
    }
    __syncthreads();
    const int b  = tid & 127;
    const int oh = tid >> 7;
    const float2* w2 = (const float2*)w0;
    for (int o = oh; o < 256; o += 2) {
        float acc = 0.f;
#pragma unroll
        for (int c = 0; c < 3; c++) {
            float2 wv = w2[(o * 3 + c) * 512 + d];
            acc += xs[c * 2 + 0][b] * wv.x + xs[c * 2 + 1][b] * wv.y;
        }
        out[((size_t)d * 128 + b) * 256 + o] = fmaxf(acc * 0.5773502691896258f, 0.f);
    }
}

// ---------------- layers 1..9: warp-mma bf16x3 GEMM (R4 geometry, 2 CTAs/SM) ----------------
// in : (p, b, c)  C=256, B=128 ; w : (256, 256, dl, 2)
// CTA: M=128(b) x N=128(o half) x K-slice (nst*32), kappa = 2c+k
// smem tiles: 128 rows x 128B (hi chunks 0-3 = kappa 0..31, lo chunks 4-7), SW128 swizzle
#define SMEM_BYTES 65536

__global__ __launch_bounds__(256, 2)
void lc_mma(const float* __restrict__ in, const float* __restrict__ w,
            float* __restrict__ out, int dl, int nst, float scale, int partial)
{
    extern __shared__ __align__(1024) char smem[];
    const uint32_t sb = s2u(smem);
    const int tid  = threadIdx.x;
    const int wid  = tid >> 5, lane = tid & 31;
    const int oh   = blockIdx.x;
    const int d    = blockIdx.y;
    const int s    = blockIdx.z;
    const int cbase = s * nst * 16;

    // ---- loader roles ----
    const int r  = tid >> 1;          // row: b for A, o_local for B
    const int h  = tid & 1;           // channel half (8 channels)
    const float*  a0p = in + ((size_t)(2 * d) * 128 + r) * 256;
    const float*  a1p = a0p + 128 * 256;
    const float2* w2  = (const float2*)w;
    const size_t  wrow = (size_t)(oh * 128 + r) * 256;

    // swizzled store offsets (constant across stages)
    const uint32_t rowb = (uint32_t)r * 128, xs_ = (uint32_t)(r & 7) << 4;
    const uint32_t offH0 = rowb + (((uint32_t)(2 * h) * 16) ^ xs_);
    const uint32_t offH1 = rowb + (((uint32_t)(2 * h + 1) * 16) ^ xs_);
    const uint32_t offL0 = rowb + (((uint32_t)(4 + 2 * h) * 16) ^ xs_);
    const uint32_t offL1 = rowb + (((uint32_t)(5 + 2 * h) * 16) ^ xs_);

    // buffer bases: A0, B0, A1, B1
    const uint32_t AB[2] = { sb, sb + 32768 };

    // ---- compute roles ----
    const int mh = wid & 1, nq = wid >> 1;
    const uint32_t co = (uint32_t)(lane >> 4) * 16;
    const uint32_t xa = (uint32_t)(lane & 7) << 4;
    uint32_t rA[4], rB[2];
#pragma unroll
    for (int mi = 0; mi < 4; mi++) rA[mi] = (uint32_t)(mh * 64 + mi * 16 + (lane & 15)) * 128;
#pragma unroll
    for (int bj = 0; bj < 2; bj++) rB[bj] = (uint32_t)(nq * 32 + bj * 16 + (lane & 15)) * 128;

    float D[4][4][4];
#pragma unroll
    for (int i = 0; i < 4; i++)
#pragma unroll
        for (int j = 0; j < 4; j++)
#pragma unroll
            for (int q = 0; q < 4; q++) D[i][j][q] = 0.f;

    float  fa[16];   // raw A (8 from each position)
    float2 fb[8];    // raw B

    auto issue_loads = [&](int t) {
        const int c0 = cbase + t * 16 + 8 * h;
        *(float4*)&fa[0]  = *(const float4*)(a0p + c0);
        *(float4*)&fa[4]  = *(const float4*)(a0p + c0 + 4);
        *(float4*)&fa[8]  = *(const float4*)(a1p + c0);
        *(float4*)&fa[12] = *(const float4*)(a1p + c0 + 4);
#pragma unroll
        for (int j = 0; j < 8; j++)
            fb[j] = w2[(wrow + (size_t)(c0 + j)) * dl + d];
    };

    auto convert_store = [&](int buf) {
        uint32_t Ah[8], Al[8], Bh[8], Bl[8];
#pragma unroll
        for (int j = 0; j < 8; j++) {
            split2(fa[j], fa[8 + j], Ah[j], Al[j]);
            split2(fb[j].x, fb[j].y, Bh[j], Bl[j]);
        }
        const uint32_t ab = AB[buf], bb = AB[buf] + 16384;
        asm volatile("st.shared.v4.b32 [%0], {%1,%2,%3,%4};" :: "r"(ab + offH0), "r"(Ah[0]), "r"(Ah[1]), "r"(Ah[2]), "r"(Ah[3]));
        asm volatile("st.shared.v4.b32 [%0], {%1,%2,%3,%4};" :: "r"(ab + offH1), "r"(Ah[4]), "r"(Ah[5]), "r"(Ah[6]), "r"(Ah[7]));
        asm volatile("st.shared.v4.b32 [%0], {%1,%2,%3,%4};" :: "r"(ab + offL0), "r"(Al[0]), "r"(Al[1]), "r"(Al[2]), "r"(Al[3]));
        asm volatile("st.shared.v4.b32 [%0], {%1,%2,%3,%4};" :: "r"(ab + offL1), "r"(Al[4]), "r"(Al[5]), "r"(Al[6]), "r"(Al[7]));
        asm volatile("st.shared.v4.b32 [%0], {%1,%2,%3,%4};" :: "r"(bb + offH0), "r"(Bh[0]), "r"(Bh[1]), "r"(Bh[2]), "r"(Bh[3]));
        asm volatile("st.shared.v4.b32 [%0], {%1,%2,%3,%4};" :: "r"(bb + offH1), "r"(Bh[4]), "r"(Bh[5]), "r"(Bh[6]), "r"(Bh[7]));
        asm volatile("st.shared.v4.b32 [%0], {%1,%2,%3,%4};" :: "r"(bb + offL0), "r"(Bl[0]), "r"(Bl[1]), "r"(Bl[2]), "r"(Bl[3]));
        asm volatile("st.shared.v4.b32 [%0], {%1,%2,%3,%4};" :: "r"(bb + offL1), "r"(Bl[4]), "r"(Bl[5]), "r"(Bl[6]), "r"(Bl[7]));
    };

    issue_loads(0);
    convert_store(0);
    __syncthreads();

    for (int t = 0; t < nst; t++) {
        const int buf = t & 1;
        if (t + 1 < nst) issue_loads(t + 1);

        const uint32_t ab = AB[buf], bb = AB[buf] + 16384;
#pragma unroll
        for (int kk = 0; kk < 2; kk++) {
            uint32_t Ahf[4][4], Alf[4][4], Bhf[2][4], Blf[2][4];
            const uint32_t khi = (uint32_t)(32 * kk) + co;
            const uint32_t klo = khi + 64;
#pragma unroll
            for (int mi = 0; mi < 4; mi++) {
                ldsm4(Ahf[mi], ab + rA[mi] + (khi ^ xa));
                ldsm4(Alf[mi], ab + rA[mi] + (klo ^ xa));
            }
#pragma unroll
            for (int bj = 0; bj < 2; bj++) {
                ldsm4(Bhf[bj], bb + rB[bj] + (khi ^ xa));
                ldsm4(Blf[bj], bb + rB[bj] + (klo ^ xa));
            }
#pragma unroll
            for (int mi = 0; mi < 4; mi++) {
#pragma unroll
                for (int nj = 0; nj < 4; nj++) {
                    const int bt = nj >> 1, bs = nj & 1;
                    mma16816(D[mi][nj], Ahf[mi], Bhf[bt][bs], Bhf[bt][bs + 2]);
                    mma16816(D[mi][nj], Alf[mi], Bhf[bt][bs], Bhf[bt][bs + 2]);
                    mma16816(D[mi][nj], Ahf[mi], Blf[bt][bs], Blf[bt][bs + 2]);
                }
            }
        }

        if (t + 1 < nst) convert_store(buf ^ 1);
        __syncthreads();
    }

    // ---- epilogue ----
    const int colq = nq * 32 + 2 * (lane & 3);
    if (partial) {
        float* pp = g_part + ((size_t)(s * 2 + oh) * dl + d) * 16384;
#pragma unroll
        for (int mi = 0; mi < 4; mi++) {
            const int b0 = mh * 64 + mi * 16 + (lane >> 2);
#pragma unroll
            for (int nj = 0; nj < 4; nj++) {
                const int col = colq + nj * 8;
                *(float2*)(pp + (size_t)b0 * 128 + col)       = make_float2(D[mi][nj][0], D[mi][nj][1]);
                *(float2*)(pp + (size_t)(b0 + 8) * 128 + col) = make_float2(D[mi][nj][2], D[mi][nj][3]);
            }
        }
    } else {
        float* op = out + (size_t)d * 128 * 256 + oh * 128;
#pragma unroll
        for (int mi = 0; mi < 4; mi++) {
            const int b0 = mh * 64 + mi * 16 + (lane >> 2);
#pragma unroll
            for (int nj = 0; nj < 4; nj++) {
                const int col = colq + nj * 8;
                float2 v0 = make_float2(fmaxf(D[mi][nj][0] * scale, 0.f), fmaxf(D[mi][nj][1] * scale, 0.f));
                float2 v1 = make_float2(fmaxf(D[mi][nj][2] * scale, 0.f), fmaxf(D[mi][nj][3] * scale, 0.f));
                *(float2*)(op + (size_t)b0 * 256 + col)       = v0;
                *(float2*)(op + (size_t)(b0 + 8) * 256 + col) = v1;
            }
        }
    }
}

// ---------------- split-K reduce + relu ----------------
__global__ void reduce_relu_kernel(const float* __restrict__ part, float* __restrict__ out,
                                   int n, int dl, int S, float scale)
{
    int idx = blockIdx.x * 256 + threadIdx.x;
    if (idx >= n) return;
    const int o  = idx & 255;
    const int b  = (idx >> 8) & 127;
    const int dd = idx >> 15;
    const int ohh = o >> 7, ol = o & 127;
    float sum = 0.f;
    for (int si = 0; si < S; si++)
        sum += part[((size_t)(si * 2 + ohh) * dl + dd) * 16384 + b * 128 + ol];
    out[idx] = fmaxf(sum * scale, 0.f);
}

// ---------------- head ----------------
__global__ void head_kernel(const float* __restrict__ act, const float* __restrict__ beta,
                            float* __restrict__ out)
{
    const int t = blockIdx.x;
    const int b = threadIdx.x;
    float s = 0.f;
#pragma unroll 8
    for (int o = 0; o < 256; o++)
        s += act[b * 256 + o] * __ldg(&beta[o * 10 + t]);
    out[b * 10 + t] = s * (1.0f / 256.0f);
}

// ---------------- launch ----------------
extern "C" void kernel_launch(void* const* d_in, const int* in_sizes, int n_in,
                              void* d_out, int out_size)
{
    const float* x = (const float*)d_in[0];
    const float* wl[10];
    for (int l = 0; l < 10; l++) wl[l] = (const float*)d_in[1 + l];
    const float* beta = (const float*)d_in[11];
    float* out = (float*)d_out;

    float *bufA, *bufB, *part;
    cudaGetSymbolAddress((void**)&bufA, g_bufA);
    cudaGetSymbolAddress((void**)&bufB, g_bufB);
    cudaGetSymbolAddress((void**)&part, g_part);

    cudaFuncSetAttribute(lc_mma, cudaFuncAttributeMaxDynamicSharedMemorySize, SMEM_BYTES);

    layer0_kernel<<<512, 256>>>(x, wl[0], bufA);

    float* cur = bufA;
    float* nxt = bufB;
    int dl = 256;
    const float scale = 0.0625f;
    for (int l = 1; l <= 9; l++) {
        int S;
        if (dl >= 128)     S = 1;
        else if (dl == 64) S = 2;
        else if (dl == 32) S = 4;
        else               S = 8;
        const int nst = 16 / S;
        if (S == 1) {
            lc_mma<<<dim3(2, dl, 1), 256, SMEM_BYTES>>>(cur, wl[l], nxt, dl, nst, scale, 0);
        } else {
            lc_mma<<<dim3(2, dl, S), 256, SMEM_BYTES>>>(cur, wl[l], part, dl, nst, scale, 1);
            const int n = dl * 32768;
            reduce_relu_kernel<<<(n + 255) / 256, 256>>>(part, nxt, n, dl, S, scale);
        }
        float* tmp = cur; cur = nxt; nxt = tmp;
        dl >>= 1;
    }

    head_kernel<<<10, 128>>>(cur, beta, out);
}

// round 10
// speedup vs baseline: 1.5420x; 1.0945x over previous
#include <cuda_runtime.h>
#include <cuda_bf16.h>
#include <cstdint>

typedef unsigned long long u64;

// ---------------- static scratch ----------------
// activations layout: (p, b, c) : act[(p*128 + b)*256 + c]
__device__ __align__(16) float g_bufA[512 * 128 * 256];   // 67 MB
__device__ __align__(16) float g_bufB[256 * 128 * 256];   // 33.5 MB
__device__ __align__(16) float g_part[4194304];           // 16.8 MB split-K partials

// ---------------- helpers ----------------
__device__ __forceinline__ uint32_t s2u(const void* p) {
    uint32_t a;
    asm("{\n\t.reg .u64 t;\n\tcvta.to.shared.u64 t, %1;\n\tcvt.u32.u64 %0, t;\n\t}" : "=r"(a) : "l"(p));
    return a;
}
// pack: first arg -> low bf16 half, second -> high half
__device__ __forceinline__ uint32_t packbf(float lo, float hi) {
    uint32_t r;
    asm("cvt.rn.bf16x2.f32 %0, %1, %2;" : "=r"(r) : "f"(hi), "f"(lo));
    return r;
}
__device__ __forceinline__ void split2(float x0, float x1, uint32_t& hi, uint32_t& lo) {
    uint32_t h = packbf(x0, x1);
    __nv_bfloat162 h2 = *(__nv_bfloat162*)&h;
    float r0 = x0 - __bfloat162float(h2.x);
    float r1 = x1 - __bfloat162float(h2.y);
    lo = packbf(r0, r1);
    hi = h;
}
__device__ __forceinline__ void ldsm4(uint32_t* r, uint32_t addr) {
    asm volatile("ldmatrix.sync.aligned.m8n8.x4.shared.b16 {%0,%1,%2,%3}, [%4];"
        : "=r"(r[0]), "=r"(r[1]), "=r"(r[2]), "=r"(r[3]) : "r"(addr));
}
__device__ __forceinline__ void mma16816(float* d, const uint32_t* a, uint32_t b0, uint32_t b1) {
    asm volatile("mma.sync.aligned.m16n8k16.row.col.f32.bf16.bf16.f32 "
        "{%0,%1,%2,%3}, {%4,%5,%6,%7}, {%8,%9}, {%0,%1,%2,%3};"
        : "+f"(d[0]), "+f"(d[1]), "+f"(d[2]), "+f"(d[3])
        : "r"(a[0]), "r"(a[1]), "r"(a[2]), "r"(a[3]), "r"(b0), "r"(b1));
}

// ---------------- layer 0 ----------------
__global__ void layer0_kernel(const float* __restrict__ x, const float* __restrict__ w0,
                              float* __restrict__ out)
{
    __shared__ float xs[6][128];
    const int d   = blockIdx.x;
    const int tid = threadIdx.x;
#pragma unroll
    for (int i = 0; i < 3; i++) {
        int e = tid + i * 256;
        int ck = e >> 7, b = e & 127;
        int c = ck >> 1, k = ck & 1;
        xs[ck][b] = x[(b * 3 + c) * 1024 + 2 * d + k];
    }
    __syncthreads();
    const int b  = tid & 127;
    const int oh = tid >> 7;
    const float2* w2 = (const float2*)w0;
    for (int o = oh; o < 256; o += 2) {
        float acc = 0.f;
#pragma unroll
        for (int c = 0; c < 3; c++) {
            float2 wv = w2[(o * 3 + c) * 512 + d];
            acc += xs[c * 2 + 0][b] * wv.x + xs[c * 2 + 1][b] * wv.y;
        }
        out[((size_t)d * 128 + b) * 256 + o] = fmaxf(acc * 0.5773502691896258f, 0.f);
    }
}

// ---------------- layers 1..9: warp-mma bf16x3, CTA 128x256, warp tile 64x64 ----------------
// in : (p, b, c)  C=256, B=128 ; w : (256, 256, dl, 2)
// CTA: M=128(b) x N=256(all o) x K-slice (nst*32), kappa = 2c+k
// smem stage: A tile 128x128B (16KB) + B tile 256x128B (32KB)
// Row layout (both tiles): linear kappa — bytes [0,64) = hi plane kappa 0..31
// (2 bytes per kappa), bytes [64,128) = lo plane. SW128 swizzle per row.
#define SMEM_BYTES 98304

__global__ __launch_bounds__(256)
void lc_mma(const float* __restrict__ in, const float* __restrict__ w,
            float* __restrict__ out, int dl, int nst, float scale, int partial)
{
    extern __shared__ __align__(1024) char smem[];
    const uint32_t sb = s2u(smem);
    const int tid  = threadIdx.x;
    const int wid  = tid >> 5, lane = tid & 31;
    const int d    = blockIdx.x;
    const int s    = blockIdx.y;
    const int cbase = s * nst * 16;

    // ---- A loader roles (as R4): row r = b, channel-half h ----
    const int r  = tid >> 1;
    const int h  = tid & 1;
    const float*  a0p = in + ((size_t)(2 * d) * 128 + r) * 256;
    const float*  a1p = a0p + 128 * 256;
    const uint32_t rowb = (uint32_t)r * 128, xs_ = (uint32_t)(r & 7) << 4;
    const uint32_t offH0 = rowb + (((uint32_t)(2 * h) * 16) ^ xs_);
    const uint32_t offH1 = rowb + (((uint32_t)(2 * h + 1) * 16) ^ xs_);
    const uint32_t offL0 = rowb + (((uint32_t)(4 + 2 * h) * 16) ^ xs_);
    const uint32_t offL1 = rowb + (((uint32_t)(5 + 2 * h) * 16) ^ xs_);

    // ---- B loader roles: one thread per o row (256 rows), 16 channels ----
    const int ob = tid;
    const float2* w2 = (const float2*)w;
    const size_t  wrow = (size_t)ob * 256;
    const uint32_t rowbB = (uint32_t)ob * 128, xsB = (uint32_t)(ob & 7) << 4;
    // 16-byte chunk offsets: hi chunks g=0..3 (channels 4g..4g+3), lo at +64
    uint32_t offBH[4], offBL[4];
#pragma unroll
    for (int g = 0; g < 4; g++) {
        offBH[g] = rowbB + (((uint32_t)(g * 16)) ^ xsB);
        offBL[g] = rowbB + (((uint32_t)(64 + g * 16)) ^ xsB);
    }

    // stage buffers: [A 16KB | B 32KB] x2
    const uint32_t ST[2] = { sb, sb + 49152 };

    // ---- compute roles: 2(M) x 4(N) warps, warp tile 64x64 ----
    const int mh = wid & 1, nq = wid >> 1;
    const uint32_t co = (uint32_t)(lane >> 4) * 16;
    const uint32_t xa = (uint32_t)(lane & 7) << 4;
    uint32_t rA[4], rB[4];
#pragma unroll
    for (int mi = 0; mi < 4; mi++) rA[mi] = (uint32_t)(mh * 64 + mi * 16 + (lane & 15)) * 128;
#pragma unroll
    for (int bj = 0; bj < 4; bj++) rB[bj] = (uint32_t)(nq * 64 + bj * 16 + (lane & 15)) * 128;

    float D[4][8][4];
#pragma unroll
    for (int i = 0; i < 4; i++)
#pragma unroll
        for (int j = 0; j < 8; j++)
#pragma unroll
            for (int q = 0; q < 4; q++) D[i][j][q] = 0.f;

    float  fa[16];    // A staging: 8 channels x 2 pos
    float2 fb[16];    // B staging: 16 channels (x,y = pos0, pos1)

    auto issue_loads = [&](int t) {
        const int c0a = cbase + t * 16 + 8 * h;
        *(float4*)&fa[0]  = *(const float4*)(a0p + c0a);
        *(float4*)&fa[4]  = *(const float4*)(a0p + c0a + 4);
        *(float4*)&fa[8]  = *(const float4*)(a1p + c0a);
        *(float4*)&fa[12] = *(const float4*)(a1p + c0a + 4);
        const int c0b = cbase + t * 16;
#pragma unroll
        for (int j = 0; j < 16; j++)
            fb[j] = w2[(wrow + (size_t)(c0b + j)) * dl + d];
    };

    auto convert_store = [&](int buf) {
        // A: word for channel c = (pos0 low, pos1 high) at linear kappa offset
        uint32_t Ah[8], Al[8];
#pragma unroll
        for (int j = 0; j < 8; j++)
            split2(fa[j], fa[8 + j], Ah[j], Al[j]);
        const uint32_t ab = ST[buf];
        asm volatile("st.shared.v4.b32 [%0], {%1,%2,%3,%4};" :: "r"(ab + offH0), "r"(Ah[0]), "r"(Ah[1]), "r"(Ah[2]), "r"(Ah[3]));
        asm volatile("st.shared.v4.b32 [%0], {%1,%2,%3,%4};" :: "r"(ab + offH1), "r"(Ah[4]), "r"(Ah[5]), "r"(Ah[6]), "r"(Ah[7]));
        asm volatile("st.shared.v4.b32 [%0], {%1,%2,%3,%4};" :: "r"(ab + offL0), "r"(Al[0]), "r"(Al[1]), "r"(Al[2]), "r"(Al[3]));
        asm volatile("st.shared.v4.b32 [%0], {%1,%2,%3,%4};" :: "r"(ab + offL1), "r"(Al[4]), "r"(Al[5]), "r"(Al[6]), "r"(Al[7]));
        // B: identical pairing — word for channel c = (pos0 low, pos1 high),
        // channels 4g..4g+3 -> hi bytes [g*16, g*16+16), lo at +64
        const uint32_t bbx = ST[buf] + 16384;
#pragma unroll
        for (int g = 0; g < 4; g++) {
            uint32_t BH[4], BL[4];
#pragma unroll
            for (int m = 0; m < 4; m++)
                split2(fb[g * 4 + m].x, fb[g * 4 + m].y, BH[m], BL[m]);
            asm volatile("st.shared.v4.b32 [%0], {%1,%2,%3,%4};" :: "r"(bbx + offBH[g]), "r"(BH[0]), "r"(BH[1]), "r"(BH[2]), "r"(BH[3]));
            asm volatile("st.shared.v4.b32 [%0], {%1,%2,%3,%4};" :: "r"(bbx + offBL[g]), "r"(BL[0]), "r"(BL[1]), "r"(BL[2]), "r"(BL[3]));
        }
    };

    issue_loads(0);
    convert_store(0);
    __syncthreads();

    for (int t = 0; t < nst; t++) {
        const int buf = t & 1;
        if (t + 1 < nst) issue_loads(t + 1);

        const uint32_t ab = ST[buf], bb = ST[buf] + 16384;
#pragma unroll
        for (int kk = 0; kk < 2; kk++) {
            const uint32_t khi = (uint32_t)(32 * kk) + co;
            const uint32_t klo = khi + 64;
            uint32_t Ahf[4][4], Alf[4][4];
#pragma unroll
            for (int mi = 0; mi < 4; mi++) {
                ldsm4(Ahf[mi], ab + rA[mi] + (khi ^ xa));
                ldsm4(Alf[mi], ab + rA[mi] + (klo ^ xa));
            }
#pragma unroll
            for (int bj = 0; bj < 4; bj++) {
                uint32_t Bhf[4], Blf[4];
                ldsm4(Bhf, bb + rB[bj] + (khi ^ xa));
                ldsm4(Blf, bb + rB[bj] + (klo ^ xa));
#pragma unroll
                for (int mi = 0; mi < 4; mi++) {
#pragma unroll
                    for (int ns = 0; ns < 2; ns++) {
                        float* dd = D[mi][bj * 2 + ns];
                        mma16816(dd, Ahf[mi], Bhf[ns], Bhf[ns + 2]);
                        mma16816(dd, Alf[mi], Bhf[ns], Bhf[ns + 2]);
                        mma16816(dd, Ahf[mi], Blf[ns], Blf[ns + 2]);
                    }
                }
            }
        }

        if (t + 1 < nst) convert_store(buf ^ 1);
        __syncthreads();
    }

    // ---- epilogue ----
    const int colq = nq * 64 + 2 * (lane & 3);
    if (partial) {
        float* pp = g_part + ((size_t)s * dl + d) * 32768;
#pragma unroll
        for (int mi = 0; mi < 4; mi++) {
            const int b0 = mh * 64 + mi * 16 + (lane >> 2);
#pragma unroll
            for (int nj = 0; nj < 8; nj++) {
                const int col = colq + nj * 8;
                *(float2*)(pp + (size_t)b0 * 256 + col)       = make_float2(D[mi][nj][0], D[mi][nj][1]);
                *(float2*)(pp + (size_t)(b0 + 8) * 256 + col) = make_float2(D[mi][nj][2], D[mi][nj][3]);
            }
        }
    } else {
        float* op = out + (size_t)d * 128 * 256;
#pragma unroll
        for (int mi = 0; mi < 4; mi++) {
            const int b0 = mh * 64 + mi * 16 + (lane >> 2);
#pragma unroll
            for (int nj = 0; nj < 8; nj++) {
                const int col = colq + nj * 8;
                float2 v0 = make_float2(fmaxf(D[mi][nj][0] * scale, 0.f), fmaxf(D[mi][nj][1] * scale, 0.f));
                float2 v1 = make_float2(fmaxf(D[mi][nj][2] * scale, 0.f), fmaxf(D[mi][nj][3] * scale, 0.f));
                *(float2*)(op + (size_t)b0 * 256 + col)       = v0;
                *(float2*)(op + (size_t)(b0 + 8) * 256 + col) = v1;
            }
        }
    }
}

// ---------------- split-K reduce + relu ----------------
__global__ void reduce_relu_kernel(const float* __restrict__ part, float* __restrict__ out,
                                   int n, int dl, int S, float scale)
{
    int idx = blockIdx.x * 256 + threadIdx.x;
    if (idx >= n) return;
    const int dd  = idx >> 15;
    const int rem = idx & 32767;
    float sum = 0.f;
    for (int si = 0; si < S; si++)
        sum += part[((size_t)si * dl + dd) * 32768 + rem];
    out[idx] = fmaxf(sum * scale, 0.f);
}

// ---------------- head ----------------
__global__ void head_kernel(const float* __restrict__ act, const float* __restrict__ beta,
                            float* __restrict__ out)
{
    const int t = blockIdx.x;
    const int b = threadIdx.x;
    float s = 0.f;
#pragma unroll 8
    for (int o = 0; o < 256; o++)
        s += act[b * 256 + o] * __ldg(&beta[o * 10 + t]);
    out[b * 10 + t] = s * (1.0f / 256.0f);
}

// ---------------- launch ----------------
extern "C" void kernel_launch(void* const* d_in, const int* in_sizes, int n_in,
                              void* d_out, int out_size)
{
    const float* x = (const float*)d_in[0];
    const float* wl[10];
    for (int l = 0; l < 10; l++) wl[l] = (const float*)d_in[1 + l];
    const float* beta = (const float*)d_in[11];
    float* out = (float*)d_out;

    float *bufA, *bufB, *part;
    cudaGetSymbolAddress((void**)&bufA, g_bufA);
    cudaGetSymbolAddress((void**)&bufB, g_bufB);
    cudaGetSymbolAddress((void**)&part, g_part);

    cudaFuncSetAttribute(lc_mma, cudaFuncAttributeMaxDynamicSharedMemorySize, SMEM_BYTES);

    layer0_kernel<<<512, 256>>>(x, wl[0], bufA);

    float* cur = bufA;
    float* nxt = bufB;
    int dl = 256;
    const float scale = 0.0625f;
    for (int l = 1; l <= 9; l++) {
        int S;
        if (dl >= 128)     S = 1;
        else if (dl == 64) S = 2;
        else if (dl == 32) S = 4;
        else               S = 8;
        const int nst = 16 / S;
        if (S == 1) {
            lc_mma<<<dim3(dl, 1), 256, SMEM_BYTES>>>(cur, wl[l], nxt, dl, nst, scale, 0);
        } else {
            lc_mma<<<dim3(dl, S), 256, SMEM_BYTES>>>(cur, wl[l], part, dl, nst, scale, 1);
            const int n = dl * 32768;
            reduce_relu_kernel<<<(n + 255) / 256, 256>>>(part, nxt, n, dl, S, scale);
        }
        float* tmp = cur; cur = nxt; nxt = tmp;
        dl >>= 1;
    }

    head_kernel<<<10, 128>>>(cur, beta, out);
}